// round 16
// baseline (speedup 1.0000x reference)
#include <cuda_runtime.h>
#include <cuda_bf16.h>
#include <cuda_fp16.h>
#include <stdint.h>

#define NB   2
#define NSEQ 2048
#define NC   1024
#define NH   16
#define ND   64
#define ATT_SCALE 0.125f

// ---- scratch (device globals, fp16) ----
__device__ __half g_hsF[(size_t)NB*NSEQ*NC];                 // activations, hi only
__device__ __half g_peF[(size_t)NB*NSEQ*NC];
__device__ __half g_WHf[5][(size_t)NC*NC], g_WLf[5][(size_t)NC*NC]; // weights hi/lo
__device__ __half g_ctxF[(size_t)NB*NSEQ*NC];                // ctx, hi only
__device__ __half g_QQF[(size_t)NB*NH*NSEQ*128];             // [q+u | q+v], hi only
__device__ __half g_KKH[(size_t)NB*NH*NSEQ*128], g_KKL[(size_t)NB*NH*NSEQ*128];
__device__ __half g_VF[(size_t)NB*NH*ND*NSEQ];               // V single fp16 (B,H,D,N)

// ---- helpers ----
__device__ __forceinline__ uint32_t pack_split_h(float x, float y, uint32_t& lo_out) {
    __half2 h = __floats2half2_rn(x, y);
    __half2 l = __floats2half2_rn(x - __half2float(__low2half(h)),
                                  y - __half2float(__high2half(h)));
    lo_out = *reinterpret_cast<uint32_t*>(&l);
    return *reinterpret_cast<uint32_t*>(&h);
}
__device__ __forceinline__ uint32_t h2_as_u32(__half2 v) {
    return *reinterpret_cast<uint32_t*>(&v);
}
__device__ __forceinline__ void cp16(uint32_t dst, const void* src) {
    asm volatile("cp.async.cg.shared.global [%0], [%1], 16;" :: "r"(dst), "l"(src));
}
__device__ __forceinline__ void cp_commit() {
    asm volatile("cp.async.commit_group;" ::: "memory");
}
template<int N> __device__ __forceinline__ void cp_wait() {
    asm volatile("cp.async.wait_group %0;" :: "n"(N) : "memory");
}
__device__ __forceinline__ void ldsm_x4(uint32_t* r, uint32_t a) {
    asm volatile("ldmatrix.sync.aligned.m8n8.x4.shared.b16 {%0,%1,%2,%3}, [%4];"
                 : "=r"(r[0]), "=r"(r[1]), "=r"(r[2]), "=r"(r[3]) : "r"(a));
}
__device__ __forceinline__ void ldsm_x2(uint32_t* r, uint32_t a) {
    asm volatile("ldmatrix.sync.aligned.m8n8.x2.shared.b16 {%0,%1}, [%2];"
                 : "=r"(r[0]), "=r"(r[1]) : "r"(a));
}

// fp16 MMA, f32 acc
#define MMAF(d, A, B0, B1)                                               \
    asm("mma.sync.aligned.m16n8k16.row.col.f32.f16.f16.f32 "             \
        "{%0,%1,%2,%3},{%4,%5,%6,%7},{%8,%9},{%0,%1,%2,%3};"             \
        : "+f"(d[0]), "+f"(d[1]), "+f"(d[2]), "+f"(d[3])                 \
        : "r"((A)[0]), "r"((A)[1]), "r"((A)[2]), "r"((A)[3]), "r"(B0), "r"(B1))

__device__ __forceinline__ int UNIT32(int r, int c) { return r * 4 + (c ^ ((r >> 1) & 3)); }
__device__ __forceinline__ int SWZ(int r, int c) { return r * 16 + (c ^ (r & 7)); }

// ============================================================================
// Merged pre-pass: activations -> single fp16; weights -> fp16 hi/lo.
// ============================================================================
__global__ void __launch_bounds__(256) split_all(
    const float4* __restrict__ hs, const float4* __restrict__ pe,
    const float4* __restrict__ wq, const float4* __restrict__ wk,
    const float4* __restrict__ wpos, const float4* __restrict__ wv,
    const float4* __restrict__ wo)
{
    const int i = blockIdx.x * 256 + threadIdx.x;
    constexpr int A = NB * NSEQ * NC / 4;
    constexpr int W = NC * NC / 4;
    if (i < 2 * A) {
        const float4 v = (i < A) ? hs[i] : pe[i - A];
        __half* F = (i < A) ? g_hsF : g_peF;
        const int off = (i < A) ? i : i - A;
        const uint32_t h0 = h2_as_u32(__floats2half2_rn(v.x, v.y));
        const uint32_t h1 = h2_as_u32(__floats2half2_rn(v.z, v.w));
        *(uint2*)(F + (size_t)off * 4) = make_uint2(h0, h1);
        return;
    }
    const int j = i - 2 * A;
    const int w = j >> 18;
    const int off = j & (W - 1);
    const float4* src;
    switch (w) {
        case 0:  src = wq;   break;
        case 1:  src = wk;   break;
        case 2:  src = wpos; break;
        case 3:  src = wv;   break;
        default: src = wo;   break;
    }
    const float4 v = src[off];
    uint32_t l0, l1;
    const uint32_t h0 = pack_split_h(v.x, v.y, l0);
    const uint32_t h1 = pack_split_h(v.z, v.w, l1);
    *(uint2*)(g_WHf[w] + (size_t)off * 4) = make_uint2(h0, h1);
    *(uint2*)(g_WLf[w] + (size_t)off * 4) = make_uint2(l0, l1);
}

// ============================================================================
// 128x128 fp16 GEMM, K=1024, BK=32, 3-deep pipeline, 2 CTA/SM.
// KIND 0 (q/k/pos/v, mode = blockIdx.z): 2-pass C = A_hi @ (B_hi + B_lo)^T.
// KIND 1 (out-proj): 1-pass C = A_hi @ B_hi^T.
// ============================================================================
template<int KIND>
__global__ void __launch_bounds__(256, 2) gemm_f16(
    const float* __restrict__ b1, const float* __restrict__ bk,
    const float* __restrict__ bv, const float* __restrict__ pbu,
    const float* __restrict__ pbv, float* __restrict__ out)
{
    constexpr int NIT = 32;
    constexpr int STG = (KIND == 0) ? 24576 : 16384;  // A 8K | Bh 8K | (Bl 8K)
    extern __shared__ __align__(16) unsigned char smem[];
    const uint32_t sb0 = (uint32_t)__cvta_generic_to_shared(smem);

    const int mode = (KIND == 0) ? blockIdx.z : 4;
    const int t = threadIdx.x, lane = t & 31, wid = t >> 5;
    const int g = lane >> 2, tg = lane & 3;
    const int wm = wid & 1, wn = wid >> 1;
    const int bm = blockIdx.y * 128, bn = blockIdx.x * 128;

    const __half* AF;
    if (KIND == 1)        AF = g_ctxF;
    else if (mode == 2)   AF = g_peF;
    else                  AF = g_hsF;
    const __half* BH = g_WHf[mode];
    const __half* BL = g_WLf[mode];

    const int row = t >> 1;
    const int ch0 = (t & 1) * 2;
    const __half* gaf = AF + (size_t)(bm + row) * 1024;
    const __half* gbh = BH + (size_t)(bn + row) * 1024;
    const __half* gbl = BL + (size_t)(bn + row) * 1024;
    uint32_t dsw[2];
    dsw[0] = (uint32_t)(UNIT32(row, ch0)     << 4);
    dsw[1] = (uint32_t)(UNIT32(row, ch0 + 1) << 4);

    #define LOAD_STAGE(buf, slice)                                          \
    {   const uint32_t st_ = sb0 + (buf) * STG;                              \
        _Pragma("unroll")                                                    \
        for (int j = 0; j < 2; j++) {                                        \
            const int e_ = (slice) * 32 + (ch0 + j) * 8;                     \
            cp16(st_ +        dsw[j], gaf + e_);                             \
            cp16(st_ + 8192 + dsw[j], gbh + e_);                             \
            if (KIND == 0) cp16(st_ + 16384 + dsw[j], gbl + e_);             \
        } }

    LOAD_STAGE(0, 0); cp_commit();
    LOAD_STAGE(1, 1); cp_commit();

    uint32_t aoff[4][2], boff[4][2];
    {
        const int rr = (lane & 7) + ((lane >> 3) & 1) * 8;
        const int cc = lane >> 4;
        const int l15 = lane & 15;
        #pragma unroll
        for (int kb = 0; kb < 2; kb++) {
            #pragma unroll
            for (int mi = 0; mi < 4; mi++)
                aoff[mi][kb] = (uint32_t)(UNIT32(wm * 64 + mi * 16 + rr, 2 * kb + cc) << 4);
            #pragma unroll
            for (int ni = 0; ni < 4; ni++)
                boff[ni][kb] = (uint32_t)(UNIT32(wn * 32 + ni * 8 + (l15 & 7),
                                                 2 * kb + (l15 >> 3)) << 4);
        }
    }

    float acc[4][4][4] = {};
    for (int it = 0; it < NIT; ++it) {
        cp_wait<1>();
        __syncthreads();
        if (it + 2 < NIT) LOAD_STAGE((it + 2) % 3, it + 2);
        cp_commit();

        const uint32_t base = sb0 + (it % 3) * STG;
        #pragma unroll
        for (int kb = 0; kb < 2; kb++) {
            uint32_t bhf[4][2], blf[4][2];
            #pragma unroll
            for (int ni = 0; ni < 4; ni++) {
                ldsm_x2(bhf[ni], base + 8192 + boff[ni][kb]);
                if (KIND == 0) ldsm_x2(blf[ni], base + 16384 + boff[ni][kb]);
            }
            #pragma unroll
            for (int mi = 0; mi < 4; mi++) {
                uint32_t ah[4];
                ldsm_x4(ah, base + aoff[mi][kb]);
                #pragma unroll
                for (int ni = 0; ni < 4; ni++)
                    MMAF(acc[mi][ni], ah, bhf[ni][0], bhf[ni][1]);
                if (KIND == 0) {
                    #pragma unroll
                    for (int ni = 0; ni < 4; ni++)
                        MMAF(acc[mi][ni], ah, blf[ni][0], blf[ni][1]);
                }
            }
        }
    }

    // ---- epilogue ----
    #pragma unroll
    for (int mi = 0; mi < 4; mi++) {
        #pragma unroll
        for (int half = 0; half < 2; half++) {
            const int grow = bm + wm * 64 + mi * 16 + g + half * 8;
            const int b_ = grow >> 11, n_ = grow & (NSEQ - 1);
            #pragma unroll
            for (int ni = 0; ni < 4; ni++) {
                const int col = bn + wn * 32 + ni * 8 + tg * 2;
                float v0 = acc[mi][ni][half * 2 + 0];
                float v1 = acc[mi][ni][half * 2 + 1];
                if (KIND == 1) {
                    *(float2*)&out[(size_t)grow * NC + col] =
                        make_float2(v0 + b1[col], v1 + b1[col + 1]);
                    continue;
                }
                const int h = col >> 6, d = col & 63;
                const size_t base128 = (((size_t)(b_ * NH + h)) * NSEQ + n_) * 128;
                if (mode == 0) {
                    v0 += b1[col]; v1 += b1[col + 1];
                    *(uint32_t*)&g_QQF[base128 + d] =
                        h2_as_u32(__floats2half2_rn(v0 + pbu[h * 64 + d],
                                                    v1 + pbu[h * 64 + d + 1]));
                    *(uint32_t*)&g_QQF[base128 + 64 + d] =
                        h2_as_u32(__floats2half2_rn(v0 + pbv[h * 64 + d],
                                                    v1 + pbv[h * 64 + d + 1]));
                } else if (mode == 1) {
                    v0 += bk[col]; v1 += bk[col + 1];
                    uint32_t lo, hi = pack_split_h(v0, v1, lo);
                    *(uint32_t*)&g_KKH[base128 + d] = hi;
                    *(uint32_t*)&g_KKL[base128 + d] = lo;
                } else if (mode == 2) {
                    uint32_t lo, hi = pack_split_h(v0, v1, lo);
                    *(uint32_t*)&g_KKH[base128 + 64 + d] = hi;
                    *(uint32_t*)&g_KKL[base128 + 64 + d] = lo;
                } else {
                    v0 += bv[col]; v1 += bv[col + 1];
                    const size_t vb = (((size_t)(b_ * NH + h)) * ND + d) * NSEQ + n_;
                    g_VF[vb]        = __float2half_rn(v0);
                    g_VF[vb + NSEQ] = __float2half_rn(v1);
                }
            }
        }
    }
}

// ============================================================================
// Fused flash attention: S 2-pass (q_hi, K hi/lo), PV 1-pass (P fp16, V fp16).
// Q frags in registers; K double-buffered 128KB, V double-buffered 32KB.
// ============================================================================
__device__ __forceinline__ void load_K(uint32_t uK,
    const __half* gh, const __half* gl, int qr, int qc0)
{
    #pragma unroll
    for (int c = 0; c < 8; c++) {
        const int ch = qc0 + c;
        cp16(uK +         (uint32_t)(SWZ(qr, ch) << 4), gh + (size_t)qr * 128 + ch * 8);
        cp16(uK + 32768 + (uint32_t)(SWZ(qr, ch) << 4), gl + (size_t)qr * 128 + ch * 8);
    }
}
__device__ __forceinline__ void load_V(uint32_t uV,
    const __half* gv, int vr, int vc0)
{
    #pragma unroll
    for (int c = 0; c < 4; c++) {
        const int ch = vc0 + c;
        cp16(uV + (uint32_t)(SWZ(vr, ch) << 4), gv + (size_t)vr * NSEQ + ch * 8);
    }
}

__global__ void __launch_bounds__(256, 1) flash_kernel()
{
    extern __shared__ __align__(16) unsigned char sm2[];
    const uint32_t sb = (uint32_t)__cvta_generic_to_shared(sm2);
    // K buffers: sb + sel*65536 (hi +0, lo +32768). V buffers: sb + 131072 + sel*16384.

    const int bh = blockIdx.y;
    const int bm = blockIdx.x * 128;
    const int t = threadIdx.x, lane = t & 31, wid = t >> 5;
    const int g = lane >> 2, tg = lane & 3;

    const __half* QF = g_QQF + (size_t)bh * NSEQ * 128 + (size_t)bm * 128;
    const __half* KH = g_KKH + (size_t)bh * NSEQ * 128;
    const __half* KL = g_KKL + (size_t)bh * NSEQ * 128;
    const __half* VF = g_VF  + (size_t)bh * ND * NSEQ;

    const int qr = t >> 1, qc0 = (t & 1) * 8;
    const int vr = t >> 2, vc0 = (t & 3) * 4;   // 256 threads cover full 64x16-chunk V tile

    load_K(sb, KH, KL, qr, qc0);
    load_V(sb + 131072, VF, vr, vc0);
    cp_commit();
    load_K(sb + 65536, KH + 128 * 128, KL + 128 * 128, qr, qc0);
    load_V(sb + 147456, VF + 128, vr, vc0);
    cp_commit();

    uint32_t qf[8][4];
    {
        const int r0 = wid * 16 + g;
        #pragma unroll
        for (int kb = 0; kb < 8; kb++) {
            const int k0 = kb * 16 + tg * 2;
            qf[kb][0] = *(const uint32_t*)&QF[(size_t)r0 * 128 + k0];
            qf[kb][1] = *(const uint32_t*)&QF[(size_t)(r0 + 8) * 128 + k0];
            qf[kb][2] = *(const uint32_t*)&QF[(size_t)r0 * 128 + k0 + 8];
            qf[kb][3] = *(const uint32_t*)&QF[(size_t)(r0 + 8) * 128 + k0 + 8];
        }
    }

    const int l15 = lane & 15;
    const int brow = (l15 & 7) + (lane >> 4) * 8;
    const int bch  = l15 >> 3;

    float m_r[2] = {-1e30f, -1e30f}, l_r[2] = {0.f, 0.f};
    float o_acc[8][4] = {};

    for (int kt = 0; kt < 16; kt++) {
        cp_wait<1>();
        __syncthreads();

        const uint32_t uK = sb + (kt & 1) * 65536;
        const uint32_t uV = sb + 131072 + (kt & 1) * 16384;

        // ---- S = Q_hi @ (K_hi + K_lo)^T: 2-pass fp16, f32 acc ----
        float acc[16][4] = {};
        #pragma unroll
        for (int kb = 0; kb < 8; kb++) {
            #pragma unroll
            for (int np = 0; np < 8; np++) {
                uint32_t kh4[4], kl4[4];
                ldsm_x4(kh4, uK +         (uint32_t)(SWZ(np * 16 + brow, kb * 2 + bch) << 4));
                ldsm_x4(kl4, uK + 32768 + (uint32_t)(SWZ(np * 16 + brow, kb * 2 + bch) << 4));
                float* a0 = acc[np * 2];
                float* a1 = acc[np * 2 + 1];
                MMAF(a0, qf[kb], kh4[0], kh4[1]);
                MMAF(a1, qf[kb], kh4[2], kh4[3]);
                MMAF(a0, qf[kb], kl4[0], kl4[1]);
                MMAF(a1, qf[kb], kl4[2], kl4[3]);
            }
        }

        // ---- row max + correction ----
        float mx0 = -1e30f, mx1 = -1e30f;
        #pragma unroll
        for (int ni = 0; ni < 16; ni++) {
            mx0 = fmaxf(mx0, fmaxf(acc[ni][0], acc[ni][1]));
            mx1 = fmaxf(mx1, fmaxf(acc[ni][2], acc[ni][3]));
        }
        mx0 *= ATT_SCALE; mx1 *= ATT_SCALE;
        mx0 = fmaxf(mx0, __shfl_xor_sync(0xFFFFFFFFu, mx0, 1));
        mx0 = fmaxf(mx0, __shfl_xor_sync(0xFFFFFFFFu, mx0, 2));
        mx1 = fmaxf(mx1, __shfl_xor_sync(0xFFFFFFFFu, mx1, 1));
        mx1 = fmaxf(mx1, __shfl_xor_sync(0xFFFFFFFFu, mx1, 2));
        const float mn0 = fmaxf(m_r[0], mx0), mn1 = fmaxf(m_r[1], mx1);
        const float c0 = __expf(m_r[0] - mn0), c1 = __expf(m_r[1] - mn1);
        m_r[0] = mn0; m_r[1] = mn1;
        #pragma unroll
        for (int nj = 0; nj < 8; nj++) {
            o_acc[nj][0] *= c0; o_acc[nj][1] *= c0;
            o_acc[nj][2] *= c1; o_acc[nj][3] *= c1;
        }

        // ---- exp interleaved with PV MMAs; P fp16, V fp16 single ----
        float s0 = 0.f, s1 = 0.f;
        auto exppair = [&](int p) {
            #pragma unroll
            for (int q = 0; q < 2; q++) {
                float* a = acc[2 * p + q];
                a[0] = __expf(fmaf(a[0], ATT_SCALE, -mn0)); s0 += a[0];
                a[1] = __expf(fmaf(a[1], ATT_SCALE, -mn0)); s0 += a[1];
                a[2] = __expf(fmaf(a[2], ATT_SCALE, -mn1)); s1 += a[2];
                a[3] = __expf(fmaf(a[3], ATT_SCALE, -mn1)); s1 += a[3];
            }
        };
        exppair(0);
        #pragma unroll
        for (int kb = 0; kb < 8; kb++) {
            uint32_t ph[4];
            ph[0] = h2_as_u32(__floats2half2_rn(acc[2 * kb][0],     acc[2 * kb][1]));
            ph[1] = h2_as_u32(__floats2half2_rn(acc[2 * kb][2],     acc[2 * kb][3]));
            ph[2] = h2_as_u32(__floats2half2_rn(acc[2 * kb + 1][0], acc[2 * kb + 1][1]));
            ph[3] = h2_as_u32(__floats2half2_rn(acc[2 * kb + 1][2], acc[2 * kb + 1][3]));
            #pragma unroll
            for (int np = 0; np < 4; np++) {
                uint32_t vh4[4];
                ldsm_x4(vh4, uV + (uint32_t)(SWZ(np * 16 + brow, kb * 2 + bch) << 4));
                MMAF(o_acc[np * 2],     ph, vh4[0], vh4[1]);
                MMAF(o_acc[np * 2 + 1], ph, vh4[2], vh4[3]);
            }
            if (kb < 7) exppair(kb + 1);
        }

        s0 += __shfl_xor_sync(0xFFFFFFFFu, s0, 1);
        s0 += __shfl_xor_sync(0xFFFFFFFFu, s0, 2);
        s1 += __shfl_xor_sync(0xFFFFFFFFu, s1, 1);
        s1 += __shfl_xor_sync(0xFFFFFFFFu, s1, 2);
        l_r[0] = l_r[0] * c0 + s0;
        l_r[1] = l_r[1] * c1 + s1;

        __syncthreads();
        if (kt + 2 < 16) {
            load_K(uK, KH + (size_t)(kt + 2) * 128 * 128,
                       KL + (size_t)(kt + 2) * 128 * 128, qr, qc0);
            load_V(uV, VF + (size_t)(kt + 2) * 128, vr, vc0);
        }
        cp_commit();
    }

    // ---- epilogue: normalize, store ctx single fp16 ----
    const int b = bh >> 4, h = bh & 15;
    const float inv0 = 1.f / l_r[0], inv1 = 1.f / l_r[1];
    const int row0 = bm + wid * 16 + g;
    #pragma unroll
    for (int nj = 0; nj < 8; nj++) {
        const int d = h * 64 + nj * 8 + tg * 2;
        const size_t i0 = ((size_t)(b * NSEQ + row0)) * NC + d;
        *(uint32_t*)&g_ctxF[i0] =
            h2_as_u32(__floats2half2_rn(o_acc[nj][0] * inv0, o_acc[nj][1] * inv0));
        const size_t i1 = ((size_t)(b * NSEQ + row0 + 8)) * NC + d;
        *(uint32_t*)&g_ctxF[i1] =
            h2_as_u32(__floats2half2_rn(o_acc[nj][2] * inv1, o_acc[nj][3] * inv1));
    }
}

// ============================================================================
extern "C" void kernel_launch(void* const* d_in, const int* in_sizes, int n_in,
                              void* d_out, int out_size)
{
    const float* hs   = (const float*)d_in[0];
    const float* pe   = (const float*)d_in[1];
    const float* Wq   = (const float*)d_in[2];
    const float* bq   = (const float*)d_in[3];
    const float* Wk   = (const float*)d_in[4];
    const float* bk   = (const float*)d_in[5];
    const float* Wv   = (const float*)d_in[6];
    const float* bv   = (const float*)d_in[7];
    const float* Wpos = (const float*)d_in[8];
    const float* pbu  = (const float*)d_in[9];
    const float* pbv  = (const float*)d_in[10];
    const float* Wo   = (const float*)d_in[11];
    const float* bo   = (const float*)d_in[12];
    float* out = (float*)d_out;

    constexpr int GEMM0_SMEM = 3 * 24576;   // 73728
    constexpr int GEMM1_SMEM = 3 * 16384;   // 49152
    constexpr int FLASH_SMEM = 131072 + 32768;  // 163840
    static int smem_set = 0;
    if (!smem_set) {
        cudaFuncSetAttribute(flash_kernel,
                             cudaFuncAttributeMaxDynamicSharedMemorySize, FLASH_SMEM);
        cudaFuncSetAttribute(gemm_f16<0>,
                             cudaFuncAttributeMaxDynamicSharedMemorySize, GEMM0_SMEM);
        cudaFuncSetAttribute(gemm_f16<1>,
                             cudaFuncAttributeMaxDynamicSharedMemorySize, GEMM1_SMEM);
        smem_set = 1;
    }

    constexpr int A = NB * NSEQ * NC / 4;
    constexpr int W = NC * NC / 4;
    split_all<<<(2 * A + 5 * W) / 256, 256>>>(
        (const float4*)hs, (const float4*)pe, (const float4*)Wq,
        (const float4*)Wk, (const float4*)Wpos, (const float4*)Wv,
        (const float4*)Wo);

    gemm_f16<0><<<dim3(NC / 128, (NB * NSEQ) / 128, 4), 256, GEMM0_SMEM>>>(
        bq, bk, bv, pbu, pbv, nullptr);

    flash_kernel<<<dim3(NSEQ / 128, NB * NH), 256, FLASH_SMEM>>>();

    gemm_f16<1><<<dim3(NC / 128, (NB * NSEQ) / 128, 1), 256, GEMM1_SMEM>>>(
        bo, nullptr, nullptr, nullptr, nullptr, out);
}

// round 17
// speedup vs baseline: 1.4326x; 1.4326x over previous
#include <cuda_runtime.h>
#include <cuda_bf16.h>
#include <cuda_fp16.h>
#include <stdint.h>

#define NB   2
#define NSEQ 2048
#define NC   1024
#define NH   16
#define ND   64
#define ATT_SCALE 0.125f

// ---- scratch (device globals, fp16) ----
__device__ __half g_hsF[(size_t)NB*NSEQ*NC];                 // activations, hi only
__device__ __half g_peF[(size_t)NB*NSEQ*NC];
__device__ __half g_WHf[5][(size_t)NC*NC], g_WLf[5][(size_t)NC*NC]; // weights hi/lo
__device__ __half g_ctxF[(size_t)NB*NSEQ*NC];                // ctx, hi only
__device__ __half g_QQF[(size_t)NB*NH*NSEQ*128];             // [q+u | q+v], hi only
__device__ __half g_KKH[(size_t)NB*NH*NSEQ*128], g_KKL[(size_t)NB*NH*NSEQ*128];
__device__ __half g_VH[(size_t)NB*NH*ND*NSEQ],   g_VL[(size_t)NB*NH*ND*NSEQ]; // (B,H,D,N)

// ---- helpers ----
__device__ __forceinline__ uint32_t pack_split_h(float x, float y, uint32_t& lo_out) {
    __half2 h = __floats2half2_rn(x, y);
    __half2 l = __floats2half2_rn(x - __half2float(__low2half(h)),
                                  y - __half2float(__high2half(h)));
    lo_out = *reinterpret_cast<uint32_t*>(&l);
    return *reinterpret_cast<uint32_t*>(&h);
}
__device__ __forceinline__ uint32_t h2_as_u32(__half2 v) {
    return *reinterpret_cast<uint32_t*>(&v);
}
__device__ __forceinline__ void cp16(uint32_t dst, const void* src) {
    asm volatile("cp.async.cg.shared.global [%0], [%1], 16;" :: "r"(dst), "l"(src));
}
__device__ __forceinline__ void cp_commit() {
    asm volatile("cp.async.commit_group;" ::: "memory");
}
template<int N> __device__ __forceinline__ void cp_wait() {
    asm volatile("cp.async.wait_group %0;" :: "n"(N) : "memory");
}
__device__ __forceinline__ void ldsm_x4(uint32_t* r, uint32_t a) {
    asm volatile("ldmatrix.sync.aligned.m8n8.x4.shared.b16 {%0,%1,%2,%3}, [%4];"
                 : "=r"(r[0]), "=r"(r[1]), "=r"(r[2]), "=r"(r[3]) : "r"(a));
}
__device__ __forceinline__ void ldsm_x2(uint32_t* r, uint32_t a) {
    asm volatile("ldmatrix.sync.aligned.m8n8.x2.shared.b16 {%0,%1}, [%2];"
                 : "=r"(r[0]), "=r"(r[1]) : "r"(a));
}

// fp16 MMA, f32 acc
#define MMAF(d, A, B0, B1)                                               \
    asm("mma.sync.aligned.m16n8k16.row.col.f32.f16.f16.f32 "             \
        "{%0,%1,%2,%3},{%4,%5,%6,%7},{%8,%9},{%0,%1,%2,%3};"             \
        : "+f"(d[0]), "+f"(d[1]), "+f"(d[2]), "+f"(d[3])                 \
        : "r"((A)[0]), "r"((A)[1]), "r"((A)[2]), "r"((A)[3]), "r"(B0), "r"(B1))

__device__ __forceinline__ int UNIT32(int r, int c) { return r * 4 + (c ^ ((r >> 1) & 3)); }
__device__ __forceinline__ int SWZ(int r, int c) { return r * 16 + (c ^ (r & 7)); }

// ============================================================================
// Merged pre-pass: activations -> single fp16; weights -> fp16 hi/lo.
// ============================================================================
__global__ void __launch_bounds__(256) split_all(
    const float4* __restrict__ hs, const float4* __restrict__ pe,
    const float4* __restrict__ wq, const float4* __restrict__ wk,
    const float4* __restrict__ wpos, const float4* __restrict__ wv,
    const float4* __restrict__ wo)
{
    const int i = blockIdx.x * 256 + threadIdx.x;
    constexpr int A = NB * NSEQ * NC / 4;
    constexpr int W = NC * NC / 4;
    if (i < 2 * A) {
        const float4 v = (i < A) ? hs[i] : pe[i - A];
        __half* F = (i < A) ? g_hsF : g_peF;
        const int off = (i < A) ? i : i - A;
        const uint32_t h0 = h2_as_u32(__floats2half2_rn(v.x, v.y));
        const uint32_t h1 = h2_as_u32(__floats2half2_rn(v.z, v.w));
        *(uint2*)(F + (size_t)off * 4) = make_uint2(h0, h1);
        return;
    }
    const int j = i - 2 * A;
    const int w = j >> 18;
    const int off = j & (W - 1);
    const float4* src;
    switch (w) {
        case 0:  src = wq;   break;
        case 1:  src = wk;   break;
        case 2:  src = wpos; break;
        case 3:  src = wv;   break;
        default: src = wo;   break;
    }
    const float4 v = src[off];
    uint32_t l0, l1;
    const uint32_t h0 = pack_split_h(v.x, v.y, l0);
    const uint32_t h1 = pack_split_h(v.z, v.w, l1);
    *(uint2*)(g_WHf[w] + (size_t)off * 4) = make_uint2(h0, h1);
    *(uint2*)(g_WLf[w] + (size_t)off * 4) = make_uint2(l0, l1);
}

// ============================================================================
// 128x128 fp16 GEMM, K=1024, BK=32, 3-deep pipeline, 2 CTA/SM.
// KIND 0 (q/k/pos/v, mode = blockIdx.z): 2-pass C = A_hi @ (B_hi + B_lo)^T.
// KIND 1 (out-proj): 1-pass C = A_hi @ B_hi^T.
// ============================================================================
template<int KIND>
__global__ void __launch_bounds__(256, 2) gemm_f16(
    const float* __restrict__ b1, const float* __restrict__ bk,
    const float* __restrict__ bv, const float* __restrict__ pbu,
    const float* __restrict__ pbv, float* __restrict__ out)
{
    constexpr int NIT = 32;
    constexpr int STG = (KIND == 0) ? 24576 : 16384;  // A 8K | Bh 8K | (Bl 8K)
    extern __shared__ __align__(16) unsigned char smem[];
    const uint32_t sb0 = (uint32_t)__cvta_generic_to_shared(smem);

    const int mode = (KIND == 0) ? blockIdx.z : 4;
    const int t = threadIdx.x, lane = t & 31, wid = t >> 5;
    const int g = lane >> 2, tg = lane & 3;
    const int wm = wid & 1, wn = wid >> 1;
    const int bm = blockIdx.y * 128, bn = blockIdx.x * 128;

    const __half* AF;
    if (KIND == 1)        AF = g_ctxF;
    else if (mode == 2)   AF = g_peF;
    else                  AF = g_hsF;
    const __half* BH = g_WHf[mode];
    const __half* BL = g_WLf[mode];

    const int row = t >> 1;
    const int ch0 = (t & 1) * 2;
    const __half* gaf = AF + (size_t)(bm + row) * 1024;
    const __half* gbh = BH + (size_t)(bn + row) * 1024;
    const __half* gbl = BL + (size_t)(bn + row) * 1024;
    uint32_t dsw[2];
    dsw[0] = (uint32_t)(UNIT32(row, ch0)     << 4);
    dsw[1] = (uint32_t)(UNIT32(row, ch0 + 1) << 4);

    #define LOAD_STAGE(buf, slice)                                          \
    {   const uint32_t st_ = sb0 + (buf) * STG;                              \
        _Pragma("unroll")                                                    \
        for (int j = 0; j < 2; j++) {                                        \
            const int e_ = (slice) * 32 + (ch0 + j) * 8;                     \
            cp16(st_ +        dsw[j], gaf + e_);                             \
            cp16(st_ + 8192 + dsw[j], gbh + e_);                             \
            if (KIND == 0) cp16(st_ + 16384 + dsw[j], gbl + e_);             \
        } }

    LOAD_STAGE(0, 0); cp_commit();
    LOAD_STAGE(1, 1); cp_commit();

    uint32_t aoff[4][2], boff[4][2];
    {
        const int rr = (lane & 7) + ((lane >> 3) & 1) * 8;
        const int cc = lane >> 4;
        const int l15 = lane & 15;
        #pragma unroll
        for (int kb = 0; kb < 2; kb++) {
            #pragma unroll
            for (int mi = 0; mi < 4; mi++)
                aoff[mi][kb] = (uint32_t)(UNIT32(wm * 64 + mi * 16 + rr, 2 * kb + cc) << 4);
            #pragma unroll
            for (int ni = 0; ni < 4; ni++)
                boff[ni][kb] = (uint32_t)(UNIT32(wn * 32 + ni * 8 + (l15 & 7),
                                                 2 * kb + (l15 >> 3)) << 4);
        }
    }

    float acc[4][4][4] = {};
    for (int it = 0; it < NIT; ++it) {
        cp_wait<1>();
        __syncthreads();
        if (it + 2 < NIT) LOAD_STAGE((it + 2) % 3, it + 2);
        cp_commit();

        const uint32_t base = sb0 + (it % 3) * STG;
        #pragma unroll
        for (int kb = 0; kb < 2; kb++) {
            uint32_t bhf[4][2], blf[4][2];
            #pragma unroll
            for (int ni = 0; ni < 4; ni++) {
                ldsm_x2(bhf[ni], base + 8192 + boff[ni][kb]);
                if (KIND == 0) ldsm_x2(blf[ni], base + 16384 + boff[ni][kb]);
            }
            #pragma unroll
            for (int mi = 0; mi < 4; mi++) {
                uint32_t ah[4];
                ldsm_x4(ah, base + aoff[mi][kb]);
                #pragma unroll
                for (int ni = 0; ni < 4; ni++)
                    MMAF(acc[mi][ni], ah, bhf[ni][0], bhf[ni][1]);
                if (KIND == 0) {
                    #pragma unroll
                    for (int ni = 0; ni < 4; ni++)
                        MMAF(acc[mi][ni], ah, blf[ni][0], blf[ni][1]);
                }
            }
        }
    }

    // ---- epilogue ----
    #pragma unroll
    for (int mi = 0; mi < 4; mi++) {
        #pragma unroll
        for (int half = 0; half < 2; half++) {
            const int grow = bm + wm * 64 + mi * 16 + g + half * 8;
            const int b_ = grow >> 11, n_ = grow & (NSEQ - 1);
            #pragma unroll
            for (int ni = 0; ni < 4; ni++) {
                const int col = bn + wn * 32 + ni * 8 + tg * 2;
                float v0 = acc[mi][ni][half * 2 + 0];
                float v1 = acc[mi][ni][half * 2 + 1];
                if (KIND == 1) {
                    *(float2*)&out[(size_t)grow * NC + col] =
                        make_float2(v0 + b1[col], v1 + b1[col + 1]);
                    continue;
                }
                const int h = col >> 6, d = col & 63;
                const size_t base128 = (((size_t)(b_ * NH + h)) * NSEQ + n_) * 128;
                if (mode == 0) {
                    v0 += b1[col]; v1 += b1[col + 1];
                    *(uint32_t*)&g_QQF[base128 + d] =
                        h2_as_u32(__floats2half2_rn(v0 + pbu[h * 64 + d],
                                                    v1 + pbu[h * 64 + d + 1]));
                    *(uint32_t*)&g_QQF[base128 + 64 + d] =
                        h2_as_u32(__floats2half2_rn(v0 + pbv[h * 64 + d],
                                                    v1 + pbv[h * 64 + d + 1]));
                } else if (mode == 1) {
                    v0 += bk[col]; v1 += bk[col + 1];
                    uint32_t lo, hi = pack_split_h(v0, v1, lo);
                    *(uint32_t*)&g_KKH[base128 + d] = hi;
                    *(uint32_t*)&g_KKL[base128 + d] = lo;
                } else if (mode == 2) {
                    uint32_t lo, hi = pack_split_h(v0, v1, lo);
                    *(uint32_t*)&g_KKH[base128 + 64 + d] = hi;
                    *(uint32_t*)&g_KKL[base128 + 64 + d] = lo;
                } else {
                    v0 += bv[col]; v1 += bv[col + 1];
                    const size_t vb = (((size_t)(b_ * NH + h)) * ND + d) * NSEQ + n_;
                    __half h0 = __float2half_rn(v0);
                    __half l0 = __float2half_rn(v0 - __half2float(h0));
                    __half h1 = __float2half_rn(v1);
                    __half l1 = __float2half_rn(v1 - __half2float(h1));
                    g_VH[vb] = h0;        g_VL[vb] = l0;
                    g_VH[vb + NSEQ] = h1; g_VL[vb + NSEQ] = l1;
                }
            }
        }
    }
}

// ============================================================================
// Fused flash attention (R14 structure): S 2-pass (q_hi, K hi/lo), PV 2-pass
// (P fp16, V hi/lo). Q frags in registers; K,V double-buffered (192KB).
// ============================================================================
__device__ __forceinline__ void load_K(uint32_t uK,
    const __half* gh, const __half* gl, int qr, int qc0)
{
    #pragma unroll
    for (int c = 0; c < 8; c++) {
        const int ch = qc0 + c;
        cp16(uK +         (uint32_t)(SWZ(qr, ch) << 4), gh + (size_t)qr * 128 + ch * 8);
        cp16(uK + 32768 + (uint32_t)(SWZ(qr, ch) << 4), gl + (size_t)qr * 128 + ch * 8);
    }
}
__device__ __forceinline__ void load_V(uint32_t uV,
    const __half* gh, const __half* gl, int vr, int vc0)
{
    #pragma unroll
    for (int c = 0; c < 4; c++) {
        const int ch = vc0 + c;
        cp16(uV +         (uint32_t)(SWZ(vr, ch) << 4), gh + (size_t)vr * NSEQ + ch * 8);
        cp16(uV + 16384 + (uint32_t)(SWZ(vr, ch) << 4), gl + (size_t)vr * NSEQ + ch * 8);
    }
}

__global__ void __launch_bounds__(256, 1) flash_kernel()
{
    extern __shared__ __align__(16) unsigned char sm2[];
    const uint32_t sb = (uint32_t)__cvta_generic_to_shared(sm2);
    // K buffers: sb + sel*65536 (hi +0, lo +32768). V: sb + 131072 + sel*32768.

    const int bh = blockIdx.y;
    const int bm = blockIdx.x * 128;
    const int t = threadIdx.x, lane = t & 31, wid = t >> 5;
    const int g = lane >> 2, tg = lane & 3;

    const __half* QF = g_QQF + (size_t)bh * NSEQ * 128 + (size_t)bm * 128;
    const __half* KH = g_KKH + (size_t)bh * NSEQ * 128;
    const __half* KL = g_KKL + (size_t)bh * NSEQ * 128;
    const __half* VH = g_VH  + (size_t)bh * ND * NSEQ;
    const __half* VL = g_VL  + (size_t)bh * ND * NSEQ;

    const int qr = t >> 1, qc0 = (t & 1) * 8;
    const int vr = t >> 2, vc0 = (t & 3) * 4;

    load_K(sb, KH, KL, qr, qc0);
    load_V(sb + 131072, VH, VL, vr, vc0);
    cp_commit();
    load_K(sb + 65536, KH + 128 * 128, KL + 128 * 128, qr, qc0);
    load_V(sb + 163840, VH + 128, VL + 128, vr, vc0);
    cp_commit();

    uint32_t qf[8][4];
    {
        const int r0 = wid * 16 + g;
        #pragma unroll
        for (int kb = 0; kb < 8; kb++) {
            const int k0 = kb * 16 + tg * 2;
            qf[kb][0] = *(const uint32_t*)&QF[(size_t)r0 * 128 + k0];
            qf[kb][1] = *(const uint32_t*)&QF[(size_t)(r0 + 8) * 128 + k0];
            qf[kb][2] = *(const uint32_t*)&QF[(size_t)r0 * 128 + k0 + 8];
            qf[kb][3] = *(const uint32_t*)&QF[(size_t)(r0 + 8) * 128 + k0 + 8];
        }
    }

    const int l15 = lane & 15;
    const int brow = (l15 & 7) + (lane >> 4) * 8;
    const int bch  = l15 >> 3;

    float m_r[2] = {-1e30f, -1e30f}, l_r[2] = {0.f, 0.f};
    float o_acc[8][4] = {};

    for (int kt = 0; kt < 16; kt++) {
        cp_wait<1>();
        __syncthreads();

        const uint32_t uK = sb + (kt & 1) * 65536;
        const uint32_t uV = sb + 131072 + (kt & 1) * 32768;

        // ---- S = Q_hi @ (K_hi + K_lo)^T: 2-pass fp16, f32 acc ----
        float acc[16][4] = {};
        #pragma unroll
        for (int kb = 0; kb < 8; kb++) {
            #pragma unroll
            for (int np = 0; np < 8; np++) {
                uint32_t kh4[4], kl4[4];
                ldsm_x4(kh4, uK +         (uint32_t)(SWZ(np * 16 + brow, kb * 2 + bch) << 4));
                ldsm_x4(kl4, uK + 32768 + (uint32_t)(SWZ(np * 16 + brow, kb * 2 + bch) << 4));
                float* a0 = acc[np * 2];
                float* a1 = acc[np * 2 + 1];
                MMAF(a0, qf[kb], kh4[0], kh4[1]);
                MMAF(a1, qf[kb], kh4[2], kh4[3]);
                MMAF(a0, qf[kb], kl4[0], kl4[1]);
                MMAF(a1, qf[kb], kl4[2], kl4[3]);
            }
        }

        // ---- row max + correction ----
        float mx0 = -1e30f, mx1 = -1e30f;
        #pragma unroll
        for (int ni = 0; ni < 16; ni++) {
            mx0 = fmaxf(mx0, fmaxf(acc[ni][0], acc[ni][1]));
            mx1 = fmaxf(mx1, fmaxf(acc[ni][2], acc[ni][3]));
        }
        mx0 *= ATT_SCALE; mx1 *= ATT_SCALE;
        mx0 = fmaxf(mx0, __shfl_xor_sync(0xFFFFFFFFu, mx0, 1));
        mx0 = fmaxf(mx0, __shfl_xor_sync(0xFFFFFFFFu, mx0, 2));
        mx1 = fmaxf(mx1, __shfl_xor_sync(0xFFFFFFFFu, mx1, 1));
        mx1 = fmaxf(mx1, __shfl_xor_sync(0xFFFFFFFFu, mx1, 2));
        const float mn0 = fmaxf(m_r[0], mx0), mn1 = fmaxf(m_r[1], mx1);
        const float c0 = __expf(m_r[0] - mn0), c1 = __expf(m_r[1] - mn1);
        m_r[0] = mn0; m_r[1] = mn1;
        #pragma unroll
        for (int nj = 0; nj < 8; nj++) {
            o_acc[nj][0] *= c0; o_acc[nj][1] *= c0;
            o_acc[nj][2] *= c1; o_acc[nj][3] *= c1;
        }

        // ---- exp interleaved with PV MMAs; P fp16, V hi/lo ----
        float s0 = 0.f, s1 = 0.f;
        auto exppair = [&](int p) {
            #pragma unroll
            for (int q = 0; q < 2; q++) {
                float* a = acc[2 * p + q];
                a[0] = __expf(fmaf(a[0], ATT_SCALE, -mn0)); s0 += a[0];
                a[1] = __expf(fmaf(a[1], ATT_SCALE, -mn0)); s0 += a[1];
                a[2] = __expf(fmaf(a[2], ATT_SCALE, -mn1)); s1 += a[2];
                a[3] = __expf(fmaf(a[3], ATT_SCALE, -mn1)); s1 += a[3];
            }
        };
        exppair(0);
        #pragma unroll
        for (int kb = 0; kb < 8; kb++) {
            uint32_t ph[4];
            ph[0] = h2_as_u32(__floats2half2_rn(acc[2 * kb][0],     acc[2 * kb][1]));
            ph[1] = h2_as_u32(__floats2half2_rn(acc[2 * kb][2],     acc[2 * kb][3]));
            ph[2] = h2_as_u32(__floats2half2_rn(acc[2 * kb + 1][0], acc[2 * kb + 1][1]));
            ph[3] = h2_as_u32(__floats2half2_rn(acc[2 * kb + 1][2], acc[2 * kb + 1][3]));
            #pragma unroll
            for (int np = 0; np < 4; np++) {
                uint32_t vh4[4], vl4[4];
                ldsm_x4(vh4, uV +         (uint32_t)(SWZ(np * 16 + brow, kb * 2 + bch) << 4));
                ldsm_x4(vl4, uV + 16384 + (uint32_t)(SWZ(np * 16 + brow, kb * 2 + bch) << 4));
                float* o0 = o_acc[np * 2];
                float* o1 = o_acc[np * 2 + 1];
                MMAF(o0, ph, vh4[0], vh4[1]);
                MMAF(o1, ph, vh4[2], vh4[3]);
                MMAF(o0, ph, vl4[0], vl4[1]);
                MMAF(o1, ph, vl4[2], vl4[3]);
            }
            if (kb < 7) exppair(kb + 1);
        }

        s0 += __shfl_xor_sync(0xFFFFFFFFu, s0, 1);
        s0 += __shfl_xor_sync(0xFFFFFFFFu, s0, 2);
        s1 += __shfl_xor_sync(0xFFFFFFFFu, s1, 1);
        s1 += __shfl_xor_sync(0xFFFFFFFFu, s1, 2);
        l_r[0] = l_r[0] * c0 + s0;
        l_r[1] = l_r[1] * c1 + s1;

        __syncthreads();
        if (kt + 2 < 16) {
            load_K(uK, KH + (size_t)(kt + 2) * 128 * 128,
                       KL + (size_t)(kt + 2) * 128 * 128, qr, qc0);
            load_V(uV, VH + (size_t)(kt + 2) * 128,
                       VL + (size_t)(kt + 2) * 128, vr, vc0);
        }
        cp_commit();
    }

    // ---- epilogue: normalize, store ctx single fp16 ----
    const int b = bh >> 4, h = bh & 15;
    const float inv0 = 1.f / l_r[0], inv1 = 1.f / l_r[1];
    const int row0 = bm + wid * 16 + g;
    #pragma unroll
    for (int nj = 0; nj < 8; nj++) {
        const int d = h * 64 + nj * 8 + tg * 2;
        const size_t i0 = ((size_t)(b * NSEQ + row0)) * NC + d;
        *(uint32_t*)&g_ctxF[i0] =
            h2_as_u32(__floats2half2_rn(o_acc[nj][0] * inv0, o_acc[nj][1] * inv0));
        const size_t i1 = ((size_t)(b * NSEQ + row0 + 8)) * NC + d;
        *(uint32_t*)&g_ctxF[i1] =
            h2_as_u32(__floats2half2_rn(o_acc[nj][2] * inv1, o_acc[nj][3] * inv1));
    }
}

// ============================================================================
extern "C" void kernel_launch(void* const* d_in, const int* in_sizes, int n_in,
                              void* d_out, int out_size)
{
    const float* hs   = (const float*)d_in[0];
    const float* pe   = (const float*)d_in[1];
    const float* Wq   = (const float*)d_in[2];
    const float* bq   = (const float*)d_in[3];
    const float* Wk   = (const float*)d_in[4];
    const float* bk   = (const float*)d_in[5];
    const float* Wv   = (const float*)d_in[6];
    const float* bv   = (const float*)d_in[7];
    const float* Wpos = (const float*)d_in[8];
    const float* pbu  = (const float*)d_in[9];
    const float* pbv  = (const float*)d_in[10];
    const float* Wo   = (const float*)d_in[11];
    const float* bo   = (const float*)d_in[12];
    float* out = (float*)d_out;

    constexpr int GEMM0_SMEM = 3 * 24576;       // 73728
    constexpr int GEMM1_SMEM = 3 * 16384;       // 49152
    constexpr int FLASH_SMEM = 196608;          // K 128KB x2 interleave + V 64KB
    static int smem_set = 0;
    if (!smem_set) {
        cudaFuncSetAttribute(flash_kernel,
                             cudaFuncAttributeMaxDynamicSharedMemorySize, FLASH_SMEM);
        cudaFuncSetAttribute(gemm_f16<0>,
                             cudaFuncAttributeMaxDynamicSharedMemorySize, GEMM0_SMEM);
        cudaFuncSetAttribute(gemm_f16<1>,
                             cudaFuncAttributeMaxDynamicSharedMemorySize, GEMM1_SMEM);
        smem_set = 1;
    }

    constexpr int A = NB * NSEQ * NC / 4;
    constexpr int W = NC * NC / 4;
    split_all<<<(2 * A + 5 * W) / 256, 256>>>(
        (const float4*)hs, (const float4*)pe, (const float4*)Wq,
        (const float4*)Wk, (const float4*)Wpos, (const float4*)Wv,
        (const float4*)Wo);

    gemm_f16<0><<<dim3(NC / 128, (NB * NSEQ) / 128, 4), 256, GEMM0_SMEM>>>(
        bq, bk, bv, pbu, pbv, nullptr);

    flash_kernel<<<dim3(NSEQ / 128, NB * NH), 256, FLASH_SMEM>>>();

    gemm_f16<1><<<dim3(NC / 128, (NB * NSEQ) / 128, 1), 256, GEMM1_SMEM>>>(
        bo, nullptr, nullptr, nullptr, nullptr, out);
}